// round 15
// baseline (speedup 1.0000x reference)
#include <cuda_runtime.h>
#include <cuda_fp16.h>
#include <cstdint>

// ===========================================================================
// GRUConv3d: implicit-im2col fp16 HMMA GEMM, block 128x256 (512 thr, 16 warps
// of 32x64, 3-stage cp.async, tensor-bound pipe balance) + wavefront slab scan.
// ===========================================================================

#define NB 2
#define NSP 32768
#define NROW 65536
#define KDIM 864            // 27 taps * 32 ci
#define MTOT 768

__device__ __align__(16) __half g_Xt[(size_t)NB * NSP * 32];   // 8 MB
__device__ __align__(16) __half g_Wh[(size_t)MTOT * KDIM];
__device__ __align__(16) __half g_Ch[(size_t)MTOT * NROW];
__device__ float                g_bias[MTOT];

// ---------------- helpers ---------------------------------------------------
__device__ __forceinline__ uint32_t smem_u32(const void* p) {
    uint32_t a;
    asm("{ .reg .u64 t; cvta.to.shared.u64 t, %1; cvt.u32.u64 %0, t; }" : "=r"(a) : "l"(p));
    return a;
}
__device__ __forceinline__ void cp16(uint32_t dst, const void* src) {
    asm volatile("cp.async.cg.shared.global [%0], [%1], 16;" :: "r"(dst), "l"(src));
}
__device__ __forceinline__ void cp16z(uint32_t dst, const void* src, uint32_t sz) {
    asm volatile("cp.async.cg.shared.global [%0], [%1], 16, %2;"
                 :: "r"(dst), "l"(src), "r"(sz));
}
#define CP_COMMIT() asm volatile("cp.async.commit_group;" ::: "memory")
#define CP_WAIT(n)  asm volatile("cp.async.wait_group %0;" :: "n"(n) : "memory")

#define LDSM4(r, a) \
    asm volatile("ldmatrix.sync.aligned.m8n8.x4.shared.b16 {%0,%1,%2,%3}, [%4];" \
                 : "=r"((r)[0]), "=r"((r)[1]), "=r"((r)[2]), "=r"((r)[3]) : "r"(a))

#define MMA16816(c, a, b0, b1) \
    asm volatile("mma.sync.aligned.m16n8k16.row.col.f32.f16.f16.f32 " \
                 "{%0,%1,%2,%3}, {%4,%5,%6,%7}, {%8,%9}, {%0,%1,%2,%3};" \
                 : "+f"((c)[0]), "+f"((c)[1]), "+f"((c)[2]), "+f"((c)[3]) \
                 : "r"((a)[0]), "r"((a)[1]), "r"((a)[2]), "r"((a)[3]), \
                   "r"(b0), "r"(b1))

// ---------------- 1) prep: x transpose (blocks 0..2047) + W prep (2048..2815)
__global__ void prep_kernel(const float* __restrict__ x,
                            const float* __restrict__ Wh, const float* __restrict__ bh,
                            const float* __restrict__ Wz, const float* __restrict__ bz,
                            const float* __restrict__ Ws, const float* __restrict__ bs)
{
    const int tid = threadIdx.x;
    if (blockIdx.x < 2048) {
        __shared__ float tile[32][33];
        const int bid = blockIdx.x;
        const int b = bid >> 10, d = (bid >> 5) & 31, h = bid & 31;
        for (int i = tid; i < 1024; i += 256) {
            int ci = i >> 5, w = i & 31;
            tile[ci][w] = x[(((b * 32 + ci) * 32 + d) * 32 + h) * 32 + w];
        }
        __syncthreads();
        __half* dst = g_Xt + ((size_t)(b * NSP) + d * 1024 + h * 32) * 32;
        for (int i = tid; i < 1024; i += 256) {
            int w = i >> 5, ci = i & 31;
            dst[w * 32 + ci] = __float2half(tile[ci][w]);
        }
    } else {
        const int m = blockIdx.x - 2048;
        const int n = m / 96, r = m % 96, g = r >> 5, co = r & 31;
        const float* Wp = (g == 0) ? Wh : ((g == 1) ? Wz : Ws);
        const float* bp = (g == 0) ? bh : ((g == 1) ? bz : bs);
        if (tid == 0) g_bias[m] = bp[n * 32 + co];
        for (int k = tid; k < KDIM; k += blockDim.x) {
            int t = k >> 5, ci = k & 31;
            g_Wh[(size_t)m * KDIM + k] =
                __float2half(Wp[((n * 32 + co) * 32 + ci) * 27 + t]);
        }
    }
}

// ---------------- 2) GEMM (implicit im2col, 128x256, 512 thr, 3-stage) -------
#define ASTR_B 80
#define REG_B_OFF 10240                     // A: 128*80
#define STAGE_B 30720                       // + B: 256*80
#define NSTG 3
#define GEMM_SMEM (NSTG * STAGE_B)          // 92160
#define NKC 27

__global__ void __launch_bounds__(512, 1)
gemm_kernel()
{
    extern __shared__ __align__(16) char sm[];
    const int tid = threadIdx.x, lane = tid & 31, wid = tid >> 5;
    const int m0 = blockIdx.x * 128;
    const int nt = blockIdx.y;              // 256 tiles of 256 rows
    const int b  = nt >> 7;
    const int d  = (nt >> 2) & 31;
    const int h0 = (nt & 3) * 8;
    const size_t n0 = (size_t)nt * 256;
    const int wm = wid & 3, wn = wid >> 2;  // 4 x 4 warps (32m x 64n each)
    const uint32_t sbase = smem_u32(sm);

    const char* gA = (const char*)g_Wh + (size_t)m0 * (KDIM * 2);
    const char* xb = (const char*)g_Xt + (size_t)b * NSP * 64;

    float acc[2][8][4];
#pragma unroll
    for (int i = 0; i < 2; ++i)
#pragma unroll
        for (int j = 0; j < 8; ++j)
#pragma unroll
            for (int q = 0; q < 4; ++q) acc[i][j][q] = 0.f;

    const int a_row = lane & 15;
    const int a_k8  = (lane >> 4) << 3;
    const int b_row = wn * 64 + (lane & 7) + ((lane >> 4) << 3);
    const int b_k8  = ((lane >> 3) & 1) << 3;

    auto load_stage = [&](int kc, int s) {
        const uint32_t st = sbase + s * STAGE_B;
        // A: 128 rows x 64B = 512 cp16 (1 per thread)
        {
            int r = tid >> 2, c = (tid & 3) << 4;
            cp16(st + r * ASTR_B + c, gA + (size_t)r * (KDIM * 2) + kc * 64 + c);
        }
        // B: 256 rows x 64B = 1024 cp16 (2 per thread), implicit im2col gather
        const int td = kc / 9, t9 = kc % 9;
        const int th = t9 / 3, tw = t9 % 3;
        const int dd = d + td - 1;
        const bool dok = (unsigned)dd < 32u;
#pragma unroll
        for (int i = tid; i < 1024; i += 512) {
            int r = i >> 2, c = (i & 3) << 4;
            int hh = h0 + (r >> 5) + th - 1;
            int ww = (r & 31) + tw - 1;
            bool valid = dok && (unsigned)hh < 32u && (unsigned)ww < 32u;
            const char* src = xb + ((size_t)(dd * 1024 + hh * 32 + ww)) * 64 + c;
            cp16z(st + REG_B_OFF + r * ASTR_B + c, src, valid ? 16u : 0u);
        }
        CP_COMMIT();
    };

    auto compute = [&](int s) {
        const uint32_t st = sbase + s * STAGE_B;
#pragma unroll
        for (int ks = 0; ks < 2; ++ks) {
            uint32_t A[2][4], B[4][4];
#pragma unroll
            for (int mt2 = 0; mt2 < 2; ++mt2) {
                uint32_t a = st + (wm * 32 + mt2 * 16 + a_row) * ASTR_B
                               + (ks * 16 + a_k8) * 2;
                LDSM4(A[mt2], a);
            }
#pragma unroll
            for (int bt = 0; bt < 4; ++bt) {
                uint32_t a = st + REG_B_OFF + (b_row + bt * 16) * ASTR_B
                               + (ks * 16 + b_k8) * 2;
                LDSM4(B[bt], a);
            }
#pragma unroll
            for (int mt2 = 0; mt2 < 2; ++mt2)
#pragma unroll
                for (int nt8 = 0; nt8 < 8; ++nt8) {
                    const uint32_t* bb = &B[nt8 >> 1][(nt8 & 1) * 2];
                    MMA16816(acc[mt2][nt8], A[mt2], bb[0], bb[1]);
                }
        }
    };

    load_stage(0, 0);
    load_stage(1, 1);
    int s = 0;
    for (int kc = 0; kc < NKC; ++kc) {
        CP_WAIT(1);
        __syncthreads();
        if (kc + 2 < NKC) {
            int s2 = s + 2; if (s2 >= NSTG) s2 -= NSTG;
            load_stage(kc + 2, s2);
        }
        compute(s);
        if (++s == NSTG) s = 0;
    }

    // epilogue: bias + sigmoid for z/s gates, store fp16
    const int rgrp = lane >> 2, cpair = lane & 3;
#pragma unroll
    for (int mt2 = 0; mt2 < 2; ++mt2) {
        const int mA = m0 + wm * 32 + mt2 * 16 + rgrp;
        const bool gate = ((mA >> 5) % 3) != 0;
        const float biasA = g_bias[mA];
        const float biasB = g_bias[mA + 8];
#pragma unroll
        for (int nt8 = 0; nt8 < 8; ++nt8) {
            size_t col = n0 + wn * 64 + nt8 * 8 + cpair * 2;
            float v0 = acc[mt2][nt8][0] + biasA;
            float v1 = acc[mt2][nt8][1] + biasA;
            float v2 = acc[mt2][nt8][2] + biasB;
            float v3 = acc[mt2][nt8][3] + biasB;
            if (gate) {
                v0 = 1.f / (1.f + __expf(-v0));
                v1 = 1.f / (1.f + __expf(-v1));
                v2 = 1.f / (1.f + __expf(-v2));
                v3 = 1.f / (1.f + __expf(-v3));
            }
            *(__half2*)(g_Ch + (size_t)mA * NROW + col) =
                __floats2half2_rn(v0, v1);
            *(__half2*)(g_Ch + (size_t)(mA + 8) * NROW + col) =
                __floats2half2_rn(v2, v3);
        }
    }
}

// ---------------- 3) scan: wavefront slabs, 1 block per (b,c,dir) ------------
__global__ void __launch_bounds__(1024)
scan_kernel(const float* __restrict__ h0v)
{
    __shared__ float buf[2][33 * 33];

    const int tid = threadIdx.x;
    const int j = tid >> 5, k = tid & 31;
    const int bc = blockIdx.x;
    const int b = bc >> 5, c = bc & 31;
    const int n = blockIdx.y;

    const int di = (n & 4) ? 1 : -1;
    const int dj = (n & 2) ? 1 : -1;
    const int dk = (n & 1) ? 1 : -1;

    const int jp = (dj > 0) ? j : 31 - j;
    const int kp = (dk > 0) ? k : 31 - k;
    const int jk = jp * 32 + kp;
    const int istep = (di > 0) ? 1024 : -1024;
    const int ibase = (di > 0) ? 0 : 31 * 1024;

    const size_t colb = (size_t)b * NSP;
    __half* hbp       = g_Ch + (size_t)(n * 96 +  0 + c) * NROW + colb + jk;
    const __half* zp  = g_Ch + (size_t)(n * 96 + 32 + c) * NROW + colb + jk;
    const __half* sp  = g_Ch + (size_t)(n * 96 + 64 + c) * NROW + colb + jk;

    const float h0 = h0v[n * 32 + c];
    for (int i = tid; i < 33 * 33; i += 1024) { buf[0][i] = h0; buf[1][i] = h0; }
    __syncthreads();

    const int rd = j * 33 + k;
    const int wr = (j + 1) * 33 + (k + 1);

    int idx = ibase;
    float z  = __half2float(zp[idx]);
    float hb = __half2float(hbp[idx]);
    float s  = __half2float(sp[idx]);

    int p = 0;
#pragma unroll 4
    for (int i = 0; i < 32; ++i) {
        const int nidx = idx + istep;
        float nz = 0.f, nhb = 0.f, ns = 0.f;
        if (i < 31) {
            nz = __half2float(zp[nidx]);
            nhb = __half2float(hbp[nidx]);
            ns = __half2float(sp[nidx]);
        }
        const float prev = buf[p][rd];
        const float h = fmaf(z, hb - prev, prev);
        hbp[idx] = __float2half(h * s);
        buf[p ^ 1][wr] = h;
        __syncthreads();
        p ^= 1;
        idx = nidx; z = nz; hb = nhb; s = ns;
    }
}

// ---------------- 4) reduce (fp16 in, fp32 out) ------------------------------
__global__ void reduce_kernel(float* __restrict__ out)
{
    const int e4 = blockIdx.x * 256 + threadIdx.x;
    const int b = e4 >> 18;
    const int c = (e4 >> 13) & 31;
    const int sp4 = e4 & 8191;
    const size_t col = ((size_t)b * NSP + sp4 * 4);
    float2 a01 = make_float2(0.f, 0.f), a23 = make_float2(0.f, 0.f);
#pragma unroll
    for (int n = 0; n < 8; ++n) {
        const __half2* p = (const __half2*)(g_Ch + (size_t)(n * 96 + c) * NROW + col);
        float2 v0 = __half22float2(p[0]);
        float2 v1 = __half22float2(p[1]);
        a01.x += v0.x; a01.y += v0.y; a23.x += v1.x; a23.y += v1.y;
    }
    *(float4*)(out + (((size_t)b * 32 + c) * NSP + sp4 * 4)) =
        make_float4(a01.x, a01.y, a23.x, a23.y);
}

// ---------------- launch -------------------------------------------------------
extern "C" void kernel_launch(void* const* d_in, const int* in_sizes, int n_in,
                              void* d_out, int out_size)
{
    const float* x   = (const float*)d_in[0];
    const float* Wh  = (const float*)d_in[1];
    const float* bh  = (const float*)d_in[2];
    const float* Wz  = (const float*)d_in[3];
    const float* bz  = (const float*)d_in[4];
    const float* Ws  = (const float*)d_in[5];
    const float* bs  = (const float*)d_in[6];
    const float* h0v = (const float*)d_in[7];
    float* out = (float*)d_out;

    cudaFuncSetAttribute(gemm_kernel, cudaFuncAttributeMaxDynamicSharedMemorySize, GEMM_SMEM);

    prep_kernel<<<2816, 256>>>(x, Wh, bh, Wz, bz, Ws, bs);
    gemm_kernel<<<dim3(6, 256), 512, GEMM_SMEM>>>();
    scan_kernel<<<dim3(64, 8), 1024>>>(h0v);
    reduce_kernel<<<2048, 256>>>(out);
}

// round 16
// speedup vs baseline: 1.3462x; 1.3462x over previous
#include <cuda_runtime.h>
#include <cuda_fp16.h>
#include <cstdint>

// ===========================================================================
// GRUConv3d: implicit-im2col fp16 HMMA GEMM (128x128 block, 256 thr, 2 CTA/SM,
// 3-stage A pipeline) with per-td x halo tile in smem (B loaded once per 9
// taps, ldmatrix gathers with per-lane addresses) + wavefront slab scan.
// ===========================================================================

#define NB 2
#define NSP 32768
#define NROW 65536
#define KDIM 864            // 27 taps * 32 ci
#define MTOT 768

__device__ __align__(16) __half g_Xt[(size_t)NB * NSP * 32];   // 8 MB
__device__ __align__(16) __half g_Wh[(size_t)MTOT * KDIM];
__device__ __align__(16) __half g_Ch[(size_t)MTOT * NROW];
__device__ float                g_bias[MTOT];

// ---------------- helpers ---------------------------------------------------
__device__ __forceinline__ uint32_t smem_u32(const void* p) {
    uint32_t a;
    asm("{ .reg .u64 t; cvta.to.shared.u64 t, %1; cvt.u32.u64 %0, t; }" : "=r"(a) : "l"(p));
    return a;
}
__device__ __forceinline__ void cp16(uint32_t dst, const void* src) {
    asm volatile("cp.async.cg.shared.global [%0], [%1], 16;" :: "r"(dst), "l"(src));
}
__device__ __forceinline__ void cp16z(uint32_t dst, const void* src, uint32_t sz) {
    asm volatile("cp.async.cg.shared.global [%0], [%1], 16, %2;"
                 :: "r"(dst), "l"(src), "r"(sz));
}
#define CP_COMMIT() asm volatile("cp.async.commit_group;" ::: "memory")
#define CP_WAIT(n)  asm volatile("cp.async.wait_group %0;" :: "n"(n) : "memory")

#define LDSM4(r, a) \
    asm volatile("ldmatrix.sync.aligned.m8n8.x4.shared.b16 {%0,%1,%2,%3}, [%4];" \
                 : "=r"((r)[0]), "=r"((r)[1]), "=r"((r)[2]), "=r"((r)[3]) : "r"(a))

#define MMA16816(c, a, b0, b1) \
    asm volatile("mma.sync.aligned.m16n8k16.row.col.f32.f16.f16.f32 " \
                 "{%0,%1,%2,%3}, {%4,%5,%6,%7}, {%8,%9}, {%0,%1,%2,%3};" \
                 : "+f"((c)[0]), "+f"((c)[1]), "+f"((c)[2]), "+f"((c)[3]) \
                 : "r"((a)[0]), "r"((a)[1]), "r"((a)[2]), "r"((a)[3]), \
                   "r"(b0), "r"(b1))

// ---------------- 1) prep: x transpose (blocks 0..2047) + W prep (2048..2815)
__global__ void prep_kernel(const float* __restrict__ x,
                            const float* __restrict__ Wh, const float* __restrict__ bh,
                            const float* __restrict__ Wz, const float* __restrict__ bz,
                            const float* __restrict__ Ws, const float* __restrict__ bs)
{
    const int tid = threadIdx.x;
    if (blockIdx.x < 2048) {
        __shared__ float tile[32][33];
        const int bid = blockIdx.x;
        const int b = bid >> 10, d = (bid >> 5) & 31, h = bid & 31;
        for (int i = tid; i < 1024; i += 256) {
            int ci = i >> 5, w = i & 31;
            tile[ci][w] = x[(((b * 32 + ci) * 32 + d) * 32 + h) * 32 + w];
        }
        __syncthreads();
        __half* dst = g_Xt + ((size_t)(b * NSP) + d * 1024 + h * 32) * 32;
        for (int i = tid; i < 1024; i += 256) {
            int w = i >> 5, ci = i & 31;
            dst[w * 32 + ci] = __float2half(tile[ci][w]);
        }
    } else {
        const int m = blockIdx.x - 2048;
        const int n = m / 96, r = m % 96, g = r >> 5, co = r & 31;
        const float* Wp = (g == 0) ? Wh : ((g == 1) ? Wz : Ws);
        const float* bp = (g == 0) ? bh : ((g == 1) ? bz : bs);
        if (tid == 0) g_bias[m] = bp[n * 32 + co];
        for (int k = tid; k < KDIM; k += blockDim.x) {
            int t = k >> 5, ci = k & 31;
            g_Wh[(size_t)m * KDIM + k] =
                __float2half(Wp[((n * 32 + co) * 32 + ci) * 27 + t]);
        }
    }
}

// ---------------- 2) GEMM (halo-B implicit im2col) ---------------------------
// A: 3 stages of 128 rows x 64B (stride 80).  X halo: 2 buffers of 6x34 voxels
// (64B data in 80B slots; h-stride 2720B).  27 chunks = taps; halo reloaded
// once per td (9 taps).
#define ASTR_B 80
#define ASTAGE_B 10240
#define HALO_OFF 30720                       // 3 * ASTAGE_B
#define HALO_B 16320                         // 6 * 34 * 80
#define GEMM_SMEM (HALO_OFF + 2 * HALO_B)    // 63360
#define NKC 27

__global__ void __launch_bounds__(256, 2)
gemm_kernel()
{
    extern __shared__ __align__(16) char sm[];
    const int tid = threadIdx.x, lane = tid & 31, wid = tid >> 5;
    const int m0 = blockIdx.x * 128;
    const int nt = blockIdx.y;               // 512 tiles of 128 rows
    const int b  = nt >> 8;
    const int d  = (nt >> 3) & 31;
    const int h0 = (nt & 7) * 4;
    const size_t n0 = (size_t)nt * 128;
    const int wm = wid & 3, wn = wid >> 2;
    const uint32_t sbase = smem_u32(sm);

    const char* gA = (const char*)g_Wh + (size_t)m0 * (KDIM * 2);
    const char* xb = (const char*)g_Xt + (size_t)b * NSP * 64;

    float acc[2][8][4];
#pragma unroll
    for (int i = 0; i < 2; ++i)
#pragma unroll
        for (int j = 0; j < 8; ++j)
#pragma unroll
            for (int q = 0; q < 4; ++q) acc[i][j][q] = 0.f;

    const int a_row = lane & 15;
    const int a_k8  = (lane >> 4) << 3;
    const int b_row = wn * 64 + (lane & 7) + ((lane >> 4) << 3);
    const int b_k8  = ((lane >> 3) & 1) << 3;

    // per-lane halo base address per bt (row -> (rh, rw) -> halo slot)
    uint32_t bBase[4];
#pragma unroll
    for (int bt = 0; bt < 4; ++bt) {
        int r = b_row + bt * 16;
        bBase[bt] = (uint32_t)((r >> 5) * 2720 + (r & 31) * 80 + b_k8 * 2);
    }

    auto load_stageA = [&](int kc, int s) {
        const uint32_t st = sbase + s * ASTAGE_B;
        for (int i = tid; i < 512; i += 256) {
            int r = i >> 2, c = (i & 3) << 4;
            cp16(st + r * ASTR_B + c, gA + (size_t)r * (KDIM * 2) + kc * 64 + c);
        }
    };

    auto load_halo = [&](int td, int p) {
        const int dd = d + td - 1;
        const bool dok = (unsigned)dd < 32u;
        const uint32_t hb = sbase + HALO_OFF + p * HALO_B;
        for (int i = tid; i < 816; i += 256) {
            int v = i >> 2, c = (i & 3) << 4;
            int rh = v / 34, wp = v % 34;
            int hh = h0 + rh - 1, ww = wp - 1;
            bool valid = dok && (unsigned)hh < 32u && (unsigned)ww < 32u;
            const char* src = xb + ((size_t)(dd * 1024 + hh * 32 + ww)) * 64 + c;
            cp16z(hb + rh * 2720 + wp * 80 + c, src, valid ? 16u : 0u);
        }
    };

    auto compute = [&](int kc, int s) {
        const uint32_t st = sbase + s * ASTAGE_B;
        const int td = kc / 9, t9 = kc % 9;
        const int th = t9 / 3, tw = t9 % 3;
        const uint32_t hOff = sbase + HALO_OFF + (uint32_t)((td & 1) * HALO_B
                             + th * 2720 + tw * 80);
#pragma unroll
        for (int ks = 0; ks < 2; ++ks) {
            uint32_t A[2][4], B[4][4];
#pragma unroll
            for (int mt2 = 0; mt2 < 2; ++mt2) {
                uint32_t a = st + (wm * 32 + mt2 * 16 + a_row) * ASTR_B
                               + (ks * 16 + a_k8) * 2;
                LDSM4(A[mt2], a);
            }
#pragma unroll
            for (int bt = 0; bt < 4; ++bt)
                LDSM4(B[bt], hOff + bBase[bt] + ks * 32);
#pragma unroll
            for (int mt2 = 0; mt2 < 2; ++mt2)
#pragma unroll
                for (int nt8 = 0; nt8 < 8; ++nt8) {
                    const uint32_t* bb = &B[nt8 >> 1][(nt8 & 1) * 2];
                    MMA16816(acc[mt2][nt8], A[mt2], bb[0], bb[1]);
                }
        }
    };

    // prologue: groups G0 = {halo0, A0}, G1 = {halo1, A1}
    load_halo(0, 0); load_stageA(0, 0); CP_COMMIT();
    load_halo(1, 1); load_stageA(1, 1); CP_COMMIT();
    int s = 0;
    for (int kc = 0; kc < NKC; ++kc) {
        if (kc < NKC - 1) { CP_WAIT(1); } else { CP_WAIT(0); }
        __syncthreads();
        if (kc + 2 < NKC) {
            int s2 = s + 2; if (s2 >= 3) s2 -= 3;
            load_stageA(kc + 2, s2);
            if (kc + 2 == 18) load_halo(2, 0);   // td=2 reuses buffer 0
            CP_COMMIT();
        }
        compute(kc, s);
        if (++s == 3) s = 0;
    }

    // epilogue: bias + sigmoid for z/s gates, store fp16
    const int rgrp = lane >> 2, cpair = lane & 3;
#pragma unroll
    for (int mt2 = 0; mt2 < 2; ++mt2) {
        const int mA = m0 + wm * 32 + mt2 * 16 + rgrp;
        const bool gate = ((mA >> 5) % 3) != 0;
        const float biasA = g_bias[mA];
        const float biasB = g_bias[mA + 8];
#pragma unroll
        for (int nt8 = 0; nt8 < 8; ++nt8) {
            size_t col = n0 + wn * 64 + nt8 * 8 + cpair * 2;
            float v0 = acc[mt2][nt8][0] + biasA;
            float v1 = acc[mt2][nt8][1] + biasA;
            float v2 = acc[mt2][nt8][2] + biasB;
            float v3 = acc[mt2][nt8][3] + biasB;
            if (gate) {
                v0 = 1.f / (1.f + __expf(-v0));
                v1 = 1.f / (1.f + __expf(-v1));
                v2 = 1.f / (1.f + __expf(-v2));
                v3 = 1.f / (1.f + __expf(-v3));
            }
            *(__half2*)(g_Ch + (size_t)mA * NROW + col) =
                __floats2half2_rn(v0, v1);
            *(__half2*)(g_Ch + (size_t)(mA + 8) * NROW + col) =
                __floats2half2_rn(v2, v3);
        }
    }
}

// ---------------- 3) scan: wavefront slabs, 1 block per (b,c,dir) ------------
__global__ void __launch_bounds__(1024)
scan_kernel(const float* __restrict__ h0v)
{
    __shared__ float buf[2][33 * 33];

    const int tid = threadIdx.x;
    const int j = tid >> 5, k = tid & 31;
    const int bc = blockIdx.x;
    const int b = bc >> 5, c = bc & 31;
    const int n = blockIdx.y;

    const int di = (n & 4) ? 1 : -1;
    const int dj = (n & 2) ? 1 : -1;
    const int dk = (n & 1) ? 1 : -1;

    const int jp = (dj > 0) ? j : 31 - j;
    const int kp = (dk > 0) ? k : 31 - k;
    const int jk = jp * 32 + kp;
    const int istep = (di > 0) ? 1024 : -1024;
    const int ibase = (di > 0) ? 0 : 31 * 1024;

    const size_t colb = (size_t)b * NSP;
    __half* hbp       = g_Ch + (size_t)(n * 96 +  0 + c) * NROW + colb + jk;
    const __half* zp  = g_Ch + (size_t)(n * 96 + 32 + c) * NROW + colb + jk;
    const __half* sp  = g_Ch + (size_t)(n * 96 + 64 + c) * NROW + colb + jk;

    const float h0 = h0v[n * 32 + c];
    for (int i = tid; i < 33 * 33; i += 1024) { buf[0][i] = h0; buf[1][i] = h0; }
    __syncthreads();

    const int rd = j * 33 + k;
    const int wr = (j + 1) * 33 + (k + 1);

    int idx = ibase;
    float z  = __half2float(zp[idx]);
    float hb = __half2float(hbp[idx]);
    float s  = __half2float(sp[idx]);

    int p = 0;
#pragma unroll 4
    for (int i = 0; i < 32; ++i) {
        const int nidx = idx + istep;
        float nz = 0.f, nhb = 0.f, ns = 0.f;
        if (i < 31) {
            nz = __half2float(zp[nidx]);
            nhb = __half2float(hbp[nidx]);
            ns = __half2float(sp[nidx]);
        }
        const float prev = buf[p][rd];
        const float h = fmaf(z, hb - prev, prev);
        hbp[idx] = __float2half(h * s);
        buf[p ^ 1][wr] = h;
        __syncthreads();
        p ^= 1;
        idx = nidx; z = nz; hb = nhb; s = ns;
    }
}

// ---------------- 4) reduce (fp16 in, fp32 out) ------------------------------
__global__ void reduce_kernel(float* __restrict__ out)
{
    const int e4 = blockIdx.x * 256 + threadIdx.x;
    const int b = e4 >> 18;
    const int c = (e4 >> 13) & 31;
    const int sp4 = e4 & 8191;
    const size_t col = ((size_t)b * NSP + sp4 * 4);
    float2 a01 = make_float2(0.f, 0.f), a23 = make_float2(0.f, 0.f);
#pragma unroll
    for (int n = 0; n < 8; ++n) {
        const __half2* p = (const __half2*)(g_Ch + (size_t)(n * 96 + c) * NROW + col);
        float2 v0 = __half22float2(p[0]);
        float2 v1 = __half22float2(p[1]);
        a01.x += v0.x; a01.y += v0.y; a23.x += v1.x; a23.y += v1.y;
    }
    *(float4*)(out + (((size_t)b * 32 + c) * NSP + sp4 * 4)) =
        make_float4(a01.x, a01.y, a23.x, a23.y);
}

// ---------------- launch -------------------------------------------------------
extern "C" void kernel_launch(void* const* d_in, const int* in_sizes, int n_in,
                              void* d_out, int out_size)
{
    const float* x   = (const float*)d_in[0];
    const float* Wh  = (const float*)d_in[1];
    const float* bh  = (const float*)d_in[2];
    const float* Wz  = (const float*)d_in[3];
    const float* bz  = (const float*)d_in[4];
    const float* Ws  = (const float*)d_in[5];
    const float* bs  = (const float*)d_in[6];
    const float* h0v = (const float*)d_in[7];
    float* out = (float*)d_out;

    cudaFuncSetAttribute(gemm_kernel, cudaFuncAttributeMaxDynamicSharedMemorySize, GEMM_SMEM);

    prep_kernel<<<2816, 256>>>(x, Wh, bh, Wz, bz, Ws, bs);
    gemm_kernel<<<dim3(6, 512), 256, GEMM_SMEM>>>();
    scan_kernel<<<dim3(64, 8), 1024>>>(h0v);
    reduce_kernel<<<2048, 256>>>(out);
}